// round 6
// baseline (speedup 1.0000x reference)
#include <cuda_runtime.h>
#include <cuda_bf16.h>
#include <cstdint>

// SimplifiedMambaBlock: the reference SSM scan has no input-injection term
// (h0 = 0, h <- exp(dt*A) * h), so h == 0 always, ssm_out == 0, y == 0,
// out_proj(0) == 0, result == x exactly. Optimal kernel = copy x -> d_out.
//
// R5: R4 retry with the ptxas-required forms. On sm_103, L2::evict_last
// ld/st must be .v8.b32 (256-bit LDG/STG). Use those: 32 B per access,
// evict_last on both loads and stores so the 67 MB working set is retained
// in the 126 MB L2 across graph replays (steady state at LTS ceiling, not
// the HBM floor both SM- and CE-path copies hit at ~6.4 TB/s).

__device__ __forceinline__ void copy32_evict_last(const uint32_t* s, uint32_t* d) {
    uint32_t r0, r1, r2, r3, r4, r5, r6, r7;
    asm volatile(
        "ld.global.L2::evict_last.v8.b32 {%0,%1,%2,%3,%4,%5,%6,%7}, [%8];"
        : "=r"(r0), "=r"(r1), "=r"(r2), "=r"(r3),
          "=r"(r4), "=r"(r5), "=r"(r6), "=r"(r7)
        : "l"(s));
    asm volatile(
        "st.global.L2::evict_last.v8.b32 [%0], {%1,%2,%3,%4,%5,%6,%7,%8};"
        :: "l"(d),
           "r"(r0), "r"(r1), "r"(r2), "r"(r3),
           "r"(r4), "r"(r5), "r"(r6), "r"(r7)
        : "memory");
}

__device__ __forceinline__ void copy32x2_evict_last(
    const uint32_t* s0, const uint32_t* s1, uint32_t* d0, uint32_t* d1)
{
    // Two independent 32B loads front-batched, then two stores.
    uint32_t a0, a1, a2, a3, a4, a5, a6, a7;
    uint32_t b0, b1, b2, b3, b4, b5, b6, b7;
    asm volatile(
        "ld.global.L2::evict_last.v8.b32 {%0,%1,%2,%3,%4,%5,%6,%7}, [%8];"
        : "=r"(a0), "=r"(a1), "=r"(a2), "=r"(a3),
          "=r"(a4), "=r"(a5), "=r"(a6), "=r"(a7)
        : "l"(s0));
    asm volatile(
        "ld.global.L2::evict_last.v8.b32 {%0,%1,%2,%3,%4,%5,%6,%7}, [%8];"
        : "=r"(b0), "=r"(b1), "=r"(b2), "=r"(b3),
          "=r"(b4), "=r"(b5), "=r"(b6), "=r"(b7)
        : "l"(s1));
    asm volatile(
        "st.global.L2::evict_last.v8.b32 [%0], {%1,%2,%3,%4,%5,%6,%7,%8};"
        :: "l"(d0),
           "r"(a0), "r"(a1), "r"(a2), "r"(a3),
           "r"(a4), "r"(a5), "r"(a6), "r"(a7)
        : "memory");
    asm volatile(
        "st.global.L2::evict_last.v8.b32 [%0], {%1,%2,%3,%4,%5,%6,%7,%8};"
        :: "l"(d1),
           "r"(b0), "r"(b1), "r"(b2), "r"(b3),
           "r"(b4), "r"(b5), "r"(b6), "r"(b7)
        : "memory");
}

__global__ __launch_bounds__(256) void mamba_identity_copy8_el(
    const uint32_t* __restrict__ src, uint32_t* __restrict__ dst, int n8)
{
    // n8 = number of 8-word (32 B) elements. Each thread copies 2 of them.
    int base = blockIdx.x * (blockDim.x * 2) + threadIdx.x;

    if (base + blockDim.x < n8) {
        copy32x2_evict_last(src + 8 * (size_t)base,
                            src + 8 * (size_t)(base + blockDim.x),
                            dst + 8 * (size_t)base,
                            dst + 8 * (size_t)(base + blockDim.x));
    } else {
        #pragma unroll
        for (int k = 0; k < 2; k++) {
            int i = base + k * blockDim.x;
            if (i < n8)
                copy32_evict_last(src + 8 * (size_t)i, dst + 8 * (size_t)i);
        }
    }
}

extern "C" void kernel_launch(void* const* d_in, const int* in_sizes, int n_in,
                              void* d_out, int out_size)
{
    const uint32_t* x = (const uint32_t*)d_in[0];   // (B, L, dim) fp32
    uint32_t* out = (uint32_t*)d_out;

    int n8 = out_size >> 3;                   // 8388608/8 = 1048576
    int threads = 256;
    int per_block = threads * 2;              // 512 x 32B per block
    int blocks = (n8 + per_block - 1) / per_block;  // 2048

    mamba_identity_copy8_el<<<blocks, threads>>>(x, out, n8);
}

// round 7
// speedup vs baseline: 1.0151x; 1.0151x over previous
#include <cuda_runtime.h>
#include <cuda_bf16.h>

// SimplifiedMambaBlock: the reference SSM scan has no input-injection term
// (h0 = 0, h <- exp(dt*A) * h), so h == 0 always, ssm_out == 0, y == 0,
// out_proj(0) == 0, result == x exactly. Optimal kernel = copy x -> d_out.
//
// R6: all bandwidth-side probes (vector width, MLP, CE path, evict_last)
// converge at 10.4-10.8 us => transfer itself is at the path cap; the
// residual above the ~8.4 us HBM floor is fixed launch structure. R2's
// 2048 CTAs @ occ 8 ran in 2 waves, paying one T_wave_trans (~2360 cyc).
// Launch exactly ONE wave: 148 SMs x 8 CTAs = 1184 blocks of 256, each
// grid-striding (2-batched for front-batched LDGs) until done.

__global__ __launch_bounds__(256) void mamba_identity_copy_persist(
    const float4* __restrict__ src, float4* __restrict__ dst, int n4)
{
    int stride = gridDim.x * blockDim.x;              // 1184*256 = 303104
    int i = blockIdx.x * blockDim.x + threadIdx.x;

    // 2097152 / 303104 = 6.92 iterations/thread.
    for (; i + stride < n4; i += 2 * stride) {
        float4 a = src[i];
        float4 b = src[i + stride];
        dst[i]          = a;
        dst[i + stride] = b;
    }
    if (i < n4) dst[i] = src[i];
}

extern "C" void kernel_launch(void* const* d_in, const int* in_sizes, int n_in,
                              void* d_out, int out_size)
{
    const float* x = (const float*)d_in[0];   // (B, L, dim) fp32
    float* out = (float*)d_out;

    int n4 = out_size >> 2;                   // 2097152 float4
    int threads = 256;
    int blocks = 148 * 8;                     // exactly one wave at occ 8

    mamba_identity_copy_persist<<<blocks, threads>>>(
        (const float4*)x, (float4*)out, n4);
}